// round 15
// baseline (speedup 1.0000x reference)
#include <cuda_runtime.h>
#include <cuda_bf16.h>
#include <cstdint>

typedef unsigned long long u64;

// Problem constants
#define B_   16
#define N_   1152
#define DP   8
#define M_   10
#define DD   16
#define NPC  96              // n per CTA
#define NCTA (N_ / NPC)      // 12 -> grid (12,10) = 120 CTAs, single wave
#define THREADS 512
#define NSER 3               // n per thread (96 / 32 nn-slots)
#define BD   (B_ * DD)       // 256

// W smem: natural GMEM layout, 96 n * 512B, ONE bulk copy
#define WROW 512
#define SW_BYTES (NPC * WROW)            // 49152
// u smem: per b, 96n*8p*4B = 3072B data at stride 3104B (16B aligned)
#define UROW 3104
#define SU_BYTES (B_ * UROW)             // 49664
#define SMEM_DYN (SW_BYTES + SU_BYTES)   // 98816
#define TX_BYTES (SW_BYTES + B_ * 3072)  // 98304
#define RP   260                         // floats; epilogue tile stride

// Partials [m][cta_n][bd]; counter zero-init, inc wraps -> self-reset each launch
__device__ float    g_partial[M_ * NCTA * BD];
__device__ unsigned g_ctr[M_];

__device__ __forceinline__ void fma2(u64& acc, u64 a, u64 b) {
    asm("fma.rn.f32x2 %0, %1, %2, %0;" : "+l"(acc) : "l"(a), "l"(b));
}
__device__ __forceinline__ u64 mul2(u64 a, u64 b) {
    u64 r; asm("mul.rn.f32x2 %0, %1, %2;" : "=l"(r) : "l"(a), "l"(b)); return r;
}
__device__ __forceinline__ uint32_t s2u(const void* p) {
    uint32_t a;
    asm("{ .reg .u64 t; cvta.to.shared.u64 t, %1; cvt.u32.u64 %0, t; }" : "=r"(a) : "l"(p));
    return a;
}
__device__ __forceinline__ void bulk_cp(uint32_t dst, const void* src, uint32_t bytes,
                                        uint32_t mbar) {
    asm volatile(
        "cp.async.bulk.shared::cta.global.mbarrier::complete_tx::bytes [%0], [%1], %2, [%3];"
        :: "r"(dst), "l"(src), "r"(bytes), "r"(mbar) : "memory");
}
__device__ __forceinline__ float collapse2(u64 a) {
    return __uint_as_float((unsigned)(a & 0xffffffffu)) +
           __uint_as_float((unsigned)(a >> 32));
}

__global__ __launch_bounds__(THREADS) void digitcaps_fused(
    const float* __restrict__ u,   // [B, N, DP]
    const float* __restrict__ W,   // [M, N, DD, DP]
    const float* __restrict__ Bp,  // [M, 1, N]
    float* __restrict__ out)       // [B, M, DD]
{
    extern __shared__ __align__(128) char smem[];
    char* sW = smem;                 // [n][d*8+p] natural, 512B/row
    char* sU = smem + SW_BYTES;      // [b][96n*8p @3104B]
    __shared__ __align__(8) unsigned long long mbar;
    __shared__ unsigned sLast;

    const int cn  = blockIdx.x;      // 0..11
    const int m   = blockIdx.y;      // 0..9
    const int tid = threadIdx.x;
    const int nb  = cn * NPC;

    const uint32_t mb = s2u(&mbar);

    if (tid == 0) {
        asm volatile("mbarrier.init.shared.b64 [%0], %1;" :: "r"(mb), "r"(1) : "memory");
        asm volatile("mbarrier.arrive.expect_tx.shared.b64 _, [%0], %1;"
                     :: "r"(mb), "r"((unsigned)TX_BYTES) : "memory");
    }
    __syncthreads();

    // ---- TMA bulk staging: 1 big W copy + 16 u rows = 17 requests total
    if (tid == 0) {
        bulk_cp(s2u(sW), W + ((size_t)m * N_ + nb) * (DD * DP), SW_BYTES, mb);
    } else if (tid <= B_) {
        const int b = tid - 1;
        bulk_cp(s2u(sU + b * UROW), u + ((size_t)b * N_ + nb) * DP, 3072, mb);
    }

    // ---- compute mapping + Bp prefetch (overlaps the TMA transfer)
    const int lane = tid & 31;
    const int wid  = tid >> 5;         // 0..15
    const int bq   = lane & 3;
    const int dq   = (lane >> 2) & 3;
    const int nnl  = lane >> 4;        // 0..1
    const int nn   = 2 * wid + nnl;    // 0..31
    const int rot  = dq + 4 * nnl;     // 0..7, distinct per (dq,nnl) -> conflict-free W LDS

    u64 sc2[NSER];
    #pragma unroll
    for (int t = 0; t < NSER; ++t) {
        const float sc = 1.0f + __ldg(&Bp[m * N_ + nb + nn + 32 * t]);
        asm("mov.b64 %0, {%1, %1};" : "=l"(sc2[t]) : "f"(sc));
    }

    // ---- wait for all 98304 bytes
    {
        uint32_t done;
        asm volatile(
            "{\n\t.reg .pred p;\n\t"
            "mbarrier.try_wait.parity.acquire.cta.shared::cta.b64 p, [%1], 0;\n\t"
            "selp.b32 %0, 1, 0, p;\n\t}"
            : "=r"(done) : "r"(mb) : "memory");
        while (!done) {
            asm volatile(
                "{\n\t.reg .pred p;\n\t"
                "mbarrier.try_wait.parity.acquire.cta.shared::cta.b64 p, [%1], 0, 0x989680;\n\t"
                "selp.b32 %0, 1, 0, p;\n\t}"
                : "=r"(done) : "r"(mb) : "memory");
        }
    }

    // ---- compute: thread = (nn, dq, bq); 4b x 4d register tile, 3 n serial
    u64 acc[4][4];
    #pragma unroll
    for (int k = 0; k < 4; ++k)
        #pragma unroll
        for (int j = 0; j < 4; ++j) acc[k][j] = 0ull;

    #pragma unroll
    for (int t = 0; t < NSER; ++t) {
        const int nt = nn + 32 * t;    // 0..95

        // W block (nt, dq): 4 d x 8 p = 128B; read chunks in rotated order so the
        // 8 (dq,nnl) groups per warp hit 8 distinct bank-quads each phase.
        const char* wp = sW + nt * WROW + dq * 128;
        u64 wreg[16];   // [j*4 + half*2 + pair]
        #pragma unroll
        for (int q = 0; q < 8; ++q) {
            const int q2 = (q + rot) & 7;
            const int j  = q2 >> 1;      // d within block
            const int h  = q2 & 1;       // p half (0: p0-3, 1: p4-7)
            ulonglong2 v = *(const ulonglong2*)(wp + q2 * 16);
            wreg[j * 4 + h * 2]     = mul2(v.x, sc2[t]);
            wreg[j * 4 + h * 2 + 1] = mul2(v.y, sc2[t]);
        }
        #pragma unroll
        for (int k = 0; k < 4; ++k) {
            const int b = bq + 4 * k;
            const char* up = sU + b * UROW + nt * 32;
            const ulonglong2 a0 = *(const ulonglong2*)(up);
            const ulonglong2 a1 = *(const ulonglong2*)(up + 16);
            const u64 uu[4] = {a0.x, a0.y, a1.x, a1.y};
            #pragma unroll
            for (int j = 0; j < 4; ++j) {
                fma2(acc[k][j], uu[0], wreg[j * 4 + 0]);
                fma2(acc[k][j], uu[1], wreg[j * 4 + 1]);
                fma2(acc[k][j], uu[2], wreg[j * 4 + 2]);
                fma2(acc[k][j], uu[3], wreg[j * 4 + 3]);
            }
        }
    }

    // ---- epilogue: collapse p-pairs, transpose-reduce over 32 nn
    __syncthreads();                 // all smem reads done before overlay
    float* sP = (float*)smem;        // [32][RP] = 33280 B overlay
    #pragma unroll
    for (int k = 0; k < 4; ++k) {
        const int b = bq + 4 * k;
        float4 v;
        v.x = collapse2(acc[k][0]);
        v.y = collapse2(acc[k][1]);
        v.z = collapse2(acc[k][2]);
        v.w = collapse2(acc[k][3]);
        *(float4*)(&sP[nn * RP + b * DD + dq * 4]) = v;
    }
    __syncthreads();

    if (tid < BD) {
        float Sp = 0.f;
        #pragma unroll
        for (int r = 0; r < 32; ++r) Sp += sP[r * RP + tid];
        g_partial[((size_t)m * NCTA + cn) * BD + tid] = Sp;
    }

    // ---- last CTA per m
    __syncthreads();
    if (tid == 0) {
        unsigned old;
        asm volatile("atom.acq_rel.gpu.global.inc.u32 %0, [%1], %2;"
                     : "=r"(old) : "l"(&g_ctr[m]), "r"((unsigned)(NCTA - 1)) : "memory");
        sLast = old;
    }
    __syncthreads();
    if (sLast != NCTA - 1) return;

    if (tid < BD) {
        const float* pm = &g_partial[(size_t)m * NCTA * BD];
        float Sv = 0.f;
        #pragma unroll
        for (int c = 0; c < NCTA; ++c)
            Sv += __ldcg(pm + (size_t)c * BD + tid);

        float n2 = Sv * Sv;
        #pragma unroll
        for (int off = 8; off >= 1; off >>= 1)
            n2 += __shfl_xor_sync(0xFFFFFFFFu, n2, off, 16);

        const float norm  = sqrtf(n2);
        const float coef  = 1.0f - expf(-norm);
        const float scale = coef / (norm + 1e-7f);

        const int b = tid >> 4;
        const int d = tid & 15;
        out[((size_t)b * M_ + m) * DD + d] = Sv * scale;
    }
}

extern "C" void kernel_launch(void* const* d_in, const int* in_sizes, int n_in,
                              void* d_out, int out_size)
{
    const float* u  = (const float*)d_in[0];   // primary_caps [16,1152,8]
    const float* W  = (const float*)d_in[1];   // W [10,1152,16,8]
    const float* Bp = (const float*)d_in[2];   // B_prior [10,1,1152]
    float* out = (float*)d_out;                // [16,10,16]

    cudaFuncSetAttribute(digitcaps_fused,
                         cudaFuncAttributeMaxDynamicSharedMemorySize, SMEM_DYN);

    dim3 grid(NCTA, M_);
    digitcaps_fused<<<grid, THREADS, SMEM_DYN>>>(u, W, Bp, out);
}

// round 16
// speedup vs baseline: 1.9672x; 1.9672x over previous
#include <cuda_runtime.h>
#include <cuda_bf16.h>
#include <cstdint>

typedef unsigned long long u64;

// Problem constants
#define B_   16
#define N_   1152
#define DP   8
#define M_   10
#define DD   16
#define NPC  96              // n per CTA
#define NCTA (N_ / NPC)      // 12 -> grid (12,10) = 120 CTAs, single wave
#define THREADS 512
#define NSER 3               // n per thread (96 / 32 nn-slots)
#define BD   (B_ * DD)       // 256

// W smem: natural GMEM layout [n][d][p], 512B per n row, ONE 48KB bulk copy
#define WROW 512
#define SW_BYTES (NPC * WROW)            // 49152
// u smem: per b, 96n*8p*4B = 3072B data at stride 3104B (16B aligned)
#define UROW 3104
#define SU_BYTES (B_ * UROW)             // 49664
#define SMEM_DYN (SW_BYTES + SU_BYTES)   // 98816
#define TX_BYTES (SW_BYTES + B_ * 3072)  // 98304
#define RP   260                         // floats; epilogue tile stride

// Partials [m][cta_n][bd]; counter zero-init, inc wraps -> self-reset each launch
__device__ float    g_partial[M_ * NCTA * BD];
__device__ unsigned g_ctr[M_];

__device__ __forceinline__ void fma2(u64& acc, u64 a, u64 b) {
    asm("fma.rn.f32x2 %0, %1, %2, %0;" : "+l"(acc) : "l"(a), "l"(b));
}
__device__ __forceinline__ u64 mul2(u64 a, u64 b) {
    u64 r; asm("mul.rn.f32x2 %0, %1, %2;" : "=l"(r) : "l"(a), "l"(b)); return r;
}
__device__ __forceinline__ uint32_t s2u(const void* p) {
    uint32_t a;
    asm("{ .reg .u64 t; cvta.to.shared.u64 t, %1; cvt.u32.u64 %0, t; }" : "=r"(a) : "l"(p));
    return a;
}
__device__ __forceinline__ void bulk_cp(uint32_t dst, const void* src, uint32_t bytes,
                                        uint32_t mbar) {
    asm volatile(
        "cp.async.bulk.shared::cta.global.mbarrier::complete_tx::bytes [%0], [%1], %2, [%3];"
        :: "r"(dst), "l"(src), "r"(bytes), "r"(mbar) : "memory");
}
__device__ __forceinline__ float collapse2(u64 a) {
    return __uint_as_float((unsigned)(a & 0xffffffffu)) +
           __uint_as_float((unsigned)(a >> 32));
}

__global__ __launch_bounds__(THREADS) void digitcaps_fused(
    const float* __restrict__ u,   // [B, N, DP]
    const float* __restrict__ W,   // [M, N, DD, DP]
    const float* __restrict__ Bp,  // [M, 1, N]
    float* __restrict__ out)       // [B, M, DD]
{
    extern __shared__ __align__(128) char smem[];
    char* sW = smem;                 // [n][d*8+p] natural, 512B/row
    char* sU = smem + SW_BYTES;      // [b][96n*8p @3104B]
    __shared__ __align__(8) unsigned long long mbar;
    __shared__ unsigned sLast;

    const int cn  = blockIdx.x;      // 0..11
    const int m   = blockIdx.y;      // 0..9
    const int tid = threadIdx.x;
    const int nb  = cn * NPC;

    const uint32_t mb = s2u(&mbar);

    if (tid == 0) {
        asm volatile("mbarrier.init.shared.b64 [%0], %1;" :: "r"(mb), "r"(1) : "memory");
        asm volatile("mbarrier.arrive.expect_tx.shared.b64 _, [%0], %1;"
                     :: "r"(mb), "r"((unsigned)TX_BYTES) : "memory");
    }
    __syncthreads();

    // ---- TMA bulk staging: 1 big W copy + 16 u rows = 17 requests total
    if (tid == 0) {
        bulk_cp(s2u(sW), W + ((size_t)m * N_ + nb) * (DD * DP), SW_BYTES, mb);
    } else if (tid <= B_) {
        const int b = tid - 1;
        bulk_cp(s2u(sU + b * UROW), u + ((size_t)b * N_ + nb) * DP, 3072, mb);
    }

    // ---- compute mapping + Bp prefetch (overlaps the TMA transfer)
    const int lane = tid & 31;
    const int wid  = tid >> 5;         // 0..15
    const int bq   = lane & 3;
    const int dq   = (lane >> 2) & 3;  // thread's digits: d = dq + 4j (strided!)
    const int nnl  = lane >> 4;        // 0..1
    const int nn   = 2 * wid + nnl;    // 0..31

    u64 sc2[NSER];
    #pragma unroll
    for (int t = 0; t < NSER; ++t) {
        const float sc = 1.0f + __ldg(&Bp[m * N_ + nb + nn + 32 * t]);
        asm("mov.b64 %0, {%1, %1};" : "=l"(sc2[t]) : "f"(sc));
    }

    // ---- wait for all 98304 bytes
    {
        uint32_t done;
        asm volatile(
            "{\n\t.reg .pred p;\n\t"
            "mbarrier.try_wait.parity.acquire.cta.shared::cta.b64 p, [%1], 0;\n\t"
            "selp.b32 %0, 1, 0, p;\n\t}"
            : "=r"(done) : "r"(mb) : "memory");
        while (!done) {
            asm volatile(
                "{\n\t.reg .pred p;\n\t"
                "mbarrier.try_wait.parity.acquire.cta.shared::cta.b64 p, [%1], 0, 0x989680;\n\t"
                "selp.b32 %0, 1, 0, p;\n\t}"
                : "=r"(done) : "r"(mb) : "memory");
        }
    }

    // ---- compute: thread = (nn, dq, bq); digits d = dq+4j, 4b x 4d, 3 n serial
    u64 acc[4][4];   // [k][j]
    #pragma unroll
    for (int k = 0; k < 4; ++k)
        #pragma unroll
        for (int j = 0; j < 4; ++j) acc[k][j] = 0ull;

    #pragma unroll
    for (int t = 0; t < NSER; ++t) {
        const int nt = nn + 32 * t;    // 0..95
        const char* wrow = sW + nt * WROW;

        // load 8 chunks (j=0..3, h=0..1) at d = dq+4j, scaled by (1+Bp)
        // group = (2*dq + h) & 7 -> the two dq's per phase hit distinct groups
        u64 wreg[16];   // [j*4 + h*2 + pair] -- all-static indexing
        #pragma unroll
        for (int j = 0; j < 4; ++j) {
            #pragma unroll
            for (int h = 0; h < 2; ++h) {
                ulonglong2 v = *(const ulonglong2*)(wrow + (dq + 4 * j) * 32 + h * 16);
                wreg[j * 4 + h * 2]     = mul2(v.x, sc2[t]);
                wreg[j * 4 + h * 2 + 1] = mul2(v.y, sc2[t]);
            }
        }
        #pragma unroll
        for (int k = 0; k < 4; ++k) {
            const int b = bq + 4 * k;
            const char* up = sU + b * UROW + nt * 32;
            const ulonglong2 a0 = *(const ulonglong2*)(up);
            const ulonglong2 a1 = *(const ulonglong2*)(up + 16);
            const u64 uu[4] = {a0.x, a0.y, a1.x, a1.y};
            #pragma unroll
            for (int j = 0; j < 4; ++j) {
                fma2(acc[k][j], uu[0], wreg[j * 4 + 0]);
                fma2(acc[k][j], uu[1], wreg[j * 4 + 1]);
                fma2(acc[k][j], uu[2], wreg[j * 4 + 2]);
                fma2(acc[k][j], uu[3], wreg[j * 4 + 3]);
            }
        }
    }

    // ---- epilogue: collapse p-pairs, transpose-reduce over 32 nn
    __syncthreads();                 // all smem reads done before overlay
    float* sP = (float*)smem;        // [32][RP] = 33280 B overlay
    #pragma unroll
    for (int k = 0; k < 4; ++k) {
        const int b = bq + 4 * k;
        #pragma unroll
        for (int j = 0; j < 4; ++j)
            sP[nn * RP + b * DD + dq + 4 * j] = collapse2(acc[k][j]);
    }
    __syncthreads();

    if (tid < BD) {
        float Sp = 0.f;
        #pragma unroll
        for (int r = 0; r < 32; ++r) Sp += sP[r * RP + tid];
        g_partial[((size_t)m * NCTA + cn) * BD + tid] = Sp;
    }

    // ---- last CTA per m
    __syncthreads();
    if (tid == 0) {
        unsigned old;
        asm volatile("atom.acq_rel.gpu.global.inc.u32 %0, [%1], %2;"
                     : "=r"(old) : "l"(&g_ctr[m]), "r"((unsigned)(NCTA - 1)) : "memory");
        sLast = old;
    }
    __syncthreads();
    if (sLast != NCTA - 1) return;

    if (tid < BD) {
        const float* pm = &g_partial[(size_t)m * NCTA * BD];
        float Sv = 0.f;
        #pragma unroll
        for (int c = 0; c < NCTA; ++c)
            Sv += __ldcg(pm + (size_t)c * BD + tid);

        float n2 = Sv * Sv;
        #pragma unroll
        for (int off = 8; off >= 1; off >>= 1)
            n2 += __shfl_xor_sync(0xFFFFFFFFu, n2, off, 16);

        const float norm  = sqrtf(n2);
        const float coef  = 1.0f - expf(-norm);
        const float scale = coef / (norm + 1e-7f);

        const int b = tid >> 4;
        const int d = tid & 15;
        out[((size_t)b * M_ + m) * DD + d] = Sv * scale;
    }
}

extern "C" void kernel_launch(void* const* d_in, const int* in_sizes, int n_in,
                              void* d_out, int out_size)
{
    const float* u  = (const float*)d_in[0];   // primary_caps [16,1152,8]
    const float* W  = (const float*)d_in[1];   // W [10,1152,16,8]
    const float* Bp = (const float*)d_in[2];   // B_prior [10,1,1152]
    float* out = (float*)d_out;                // [16,10,16]

    cudaFuncSetAttribute(digitcaps_fused,
                         cudaFuncAttributeMaxDynamicSharedMemorySize, SMEM_DYN);

    dim3 grid(NCTA, M_);
    digitcaps_fused<<<grid, THREADS, SMEM_DYN>>>(u, W, Bp, out);
}